// round 1
// baseline (speedup 1.0000x reference)
#include <cuda_runtime.h>
#include <cuda_bf16.h>
#include <math.h>

#define F_N   10000
#define H_N   64
#define G_N   (4 * H_N)      // 256 gates
#define IN_N  (H_N + 1)      // 65
#define OUT_PRED_OFF 0
#define OUT_H_OFF    2
#define OUT_C_OFF    (2 + F_N * H_N)

__device__ float g_sumC[H_N];
__device__ float g_sumH[H_N];

__device__ __forceinline__ float sigmoidf_(float x) {
    return 1.0f / (1.0f + expf(-x));
}

__global__ void zero_kernel() {
    int t = threadIdx.x;
    if (t < H_N) { g_sumC[t] = 0.0f; g_sumH[t] = 0.0f; }
}

__global__ __launch_bounds__(256) void cell_kernel(
    const int*  __restrict__ tim_p,
    const float* __restrict__ X,
    const int*  __restrict__ mask,
    const int*  __restrict__ last_occ,
    const float* __restrict__ Ht,
    const float* __restrict__ c_t,
    const float* __restrict__ W,       // [F, 256, 65]
    const float* __restrict__ Bias,    // [F, 256]
    const float* __restrict__ xTw,     // [F, 64]
    const float* __restrict__ xTb,     // [F, 64]
    const float* __restrict__ delTw,   // [F, 128]
    const float* __restrict__ cinw,    // [F, 64]
    const float* __restrict__ cfw,     // [F, 64]
    const float* __restrict__ coutw,   // [F, 64]
    float* __restrict__ out)           // full output buffer
{
    const int f   = blockIdx.x;
    const int tid = threadIdx.x;
    const int lane = tid & 31;
    const int warp = tid >> 5;

    __shared__ float s_in[IN_N];       // [X[f], Ht[f,:]]
    __shared__ float s_gates[G_N];
    __shared__ float s_ct[H_N];

    if (tid == 0) s_in[0] = X[f];
    if (tid < H_N) {
        s_in[1 + tid] = Ht[(size_t)f * H_N + tid];
        s_ct[tid]     = c_t[tid];
    }
    __syncthreads();

    // --- batched mat-vec: 8 warps x 32 gate rows, 65-wide dot each ---
    const float* Wf = W + (size_t)f * G_N * IN_N;
    #pragma unroll 4
    for (int i = 0; i < 32; i++) {
        const int g = warp * 32 + i;
        const float* row = Wf + (size_t)g * IN_N;
        float acc = row[lane] * s_in[lane] + row[lane + 32] * s_in[lane + 32];
        if (lane == 0) acc += row[64] * s_in[64];
        #pragma unroll
        for (int o = 16; o > 0; o >>= 1)
            acc += __shfl_xor_sync(0xFFFFFFFFu, acc, o);
        if (lane == 0) s_gates[g] = acc + Bias[(size_t)f * G_N + g];
    }
    __syncthreads();

    // --- cell elementwise, 64 threads ---
    if (tid < H_N) {
        const int h = tid;
        const size_t fh = (size_t)f * H_N + h;
        const float ct    = s_ct[h];
        const float delta = (float)(*tim_p) - (float)last_occ[f];

        const float gi     = sigmoidf_(s_gates[h]         + cinw[fh] * ct);
        const float gf     = sigmoidf_(s_gates[H_N + h]   + cfw[fh]  * ct);
        const float go_pre = s_gates[2 * H_N + h];
        const float pre_c  = tanhf(s_gates[3 * H_N + h]);

        const float xmT = xTw[fh] * s_in[0] + xTb[fh];
        const float dTt = delTw[(size_t)f * 2 * H_N + h]       * delta;
        const float dTo = delTw[(size_t)f * 2 * H_N + H_N + h] * delta;
        const float Tt  = sigmoidf_(xmT + dTt);

        const float aggc = gf * ct + gi * Tt * pre_c;
        const float go   = sigmoidf_(go_pre + coutw[fh] * aggc + dTo);
        const float hn   = go * tanhf(aggc);

        const float mf = (mask[f] == 1) ? 1.0f : 0.0f;
        out[OUT_H_OFF + fh] = mf * hn;
        if (mf != 0.0f) {
            atomicAdd(&g_sumC[h], aggc);
            atomicAdd(&g_sumH[h], hn);
        }
    }
}

__global__ __launch_bounds__(128) void head_kernel(
    const int*  __restrict__ mask,
    const float* __restrict__ w1,   // [128,128]
    const float* __restrict__ b1,   // [128]
    const float* __restrict__ w2,   // [2,128]
    const float* __restrict__ b2,   // [2]
    float* __restrict__ out)
{
    const int tid = threadIdx.x;
    __shared__ float s_inp[2 * H_N];
    __shared__ float s_hid[2 * H_N];
    __shared__ int   s_red[128];
    __shared__ float s_log[2];

    // count observed features
    int c = 0;
    for (int i = tid; i < F_N; i += 128) c += (mask[i] == 1);
    s_red[tid] = c;
    __syncthreads();
    #pragma unroll
    for (int o = 64; o > 0; o >>= 1) {
        if (tid < o) s_red[tid] += s_red[tid + o];
        __syncthreads();
    }
    const float cnt = fmaxf((float)s_red[0], 1.0f);

    if (tid < H_N) {
        const float Cc = g_sumC[tid] / cnt;
        const float Hm = g_sumH[tid] / cnt;
        s_inp[tid]       = Cc;
        s_inp[H_N + tid] = Hm;
        out[OUT_C_OFF + tid] = Cc;
    }
    __syncthreads();

    // hidden = relu(w1 @ inp + b1)
    {
        float acc = b1[tid];
        #pragma unroll 8
        for (int k = 0; k < 2 * H_N; k++)
            acc += w1[tid * (2 * H_N) + k] * s_inp[k];
        s_hid[tid] = fmaxf(acc, 0.0f);
    }
    __syncthreads();

    if (tid < 2) {
        float l = b2[tid];
        for (int k = 0; k < 2 * H_N; k++)
            l += w2[tid * (2 * H_N) + k] * s_hid[k];
        s_log[tid] = l;
    }
    __syncthreads();

    if (tid == 0) {
        const float m  = fmaxf(s_log[0], s_log[1]);
        const float e0 = expf(s_log[0] - m);
        const float e1 = expf(s_log[1] - m);
        const float inv = 1.0f / (e0 + e1);
        out[OUT_PRED_OFF + 0] = e0 * inv;
        out[OUT_PRED_OFF + 1] = e1 * inv;
    }
}

extern "C" void kernel_launch(void* const* d_in, const int* in_sizes, int n_in,
                              void* d_out, int out_size) {
    const int*   tim       = (const int*)  d_in[0];
    const float* X         = (const float*)d_in[1];
    // d_in[2] = X_hap (unused by reference)
    const int*   mask      = (const int*)  d_in[3];
    const int*   last_occ  = (const int*)  d_in[4];
    const float* Ht        = (const float*)d_in[5];
    // d_in[6] = Ct (unused by reference)
    const float* c_t       = (const float*)d_in[7];
    const float* W         = (const float*)d_in[8];
    const float* Bias      = (const float*)d_in[9];
    const float* xTw       = (const float*)d_in[10];
    const float* xTb       = (const float*)d_in[11];
    const float* delTw     = (const float*)d_in[12];
    const float* cinw      = (const float*)d_in[13];
    const float* cfw       = (const float*)d_in[14];
    const float* coutw     = (const float*)d_in[15];
    const float* w1        = (const float*)d_in[16];
    const float* b1        = (const float*)d_in[17];
    const float* w2        = (const float*)d_in[18];
    const float* b2        = (const float*)d_in[19];
    float* out = (float*)d_out;

    zero_kernel<<<1, 128>>>();
    cell_kernel<<<F_N, 256>>>(tim, X, mask, last_occ, Ht, c_t,
                              W, Bias, xTw, xTb, delTw, cinw, cfw, coutw, out);
    head_kernel<<<1, 128>>>(mask, w1, b1, w2, b2, out);
}